// round 2
// baseline (speedup 1.0000x reference)
#include <cuda_runtime.h>

#define BATCH 8
#define NPTS  8192
#define NS    2048      // S = 0.25 * N
#define KNB   32        // nsample
#define C1    64
#define C2    64
#define C3    128

// scratch: new_xyz coords shared between the two kernels
__device__ float g_new_xyz[BATCH * NS * 3];

// XLA-exact squared distance: ((dx*dx + dy*dy) + dz*dz), no FMA contraction
__device__ __forceinline__ float sqdist_xla(float dx, float dy, float dz) {
    return __fadd_rn(__fadd_rn(__fmul_rn(dx, dx), __fmul_rn(dy, dy)),
                     __fmul_rn(dz, dz));
}

// ---------------------------------------------------------------------------
// Kernel 1: farthest point sampling. One CTA (1024 threads) per batch.
// All 8192 points + running min-dist live in registers (8 points / thread).
// Per iteration: dist update + block-wide argmax (tie-break: lowest index,
// matching jnp.argmax first-occurrence), winner publishes next centroid.
// ---------------------------------------------------------------------------
__global__ __launch_bounds__(1024) void fps_kernel(const float* __restrict__ xyz,
                                                   float* __restrict__ out)
{
    const int b   = blockIdx.x;
    const int tid = threadIdx.x;
    const float* P = xyz + b * NPTS * 3;

    __shared__ float sCx, sCy, sCz;
    __shared__ int   sBI;
    __shared__ float swv[32];
    __shared__ int   swi[32];

    float px[8], py[8], pz[8], dist[8];
#pragma unroll
    for (int j = 0; j < 8; j++) {
        int idx = tid + j * 1024;
        px[j] = P[idx * 3 + 0];
        py[j] = P[idx * 3 + 1];
        pz[j] = P[idx * 3 + 2];
        dist[j] = 1e10f;
    }
    if (tid == 0) { sCx = P[0]; sCy = P[1]; sCz = P[2]; sBI = 0; }
    __syncthreads();

    for (int s = 0; s < NS; s++) {
        const float cx = sCx, cy = sCy, cz = sCz;
        if (tid == 0) {
            // write transposed new_xyz directly into output (B,3,S)
            int o = b * 3 * NS + s;
            out[o]           = cx;
            out[o + NS]      = cy;
            out[o + 2 * NS]  = cz;
            int c = (b * NS + s) * 3;
            g_new_xyz[c]     = cx;
            g_new_xyz[c + 1] = cy;
            g_new_xyz[c + 2] = cz;
        }

        float bv = -1.0f;
        int   bi = 0;
#pragma unroll
        for (int j = 0; j < 8; j++) {
            float dx = px[j] - cx;
            float dy = py[j] - cy;
            float dz = pz[j] - cz;
            float d  = sqdist_xla(dx, dy, dz);
            float nd = fminf(dist[j], d);
            dist[j] = nd;
            if (nd > bv) { bv = nd; bi = tid + j * 1024; }  // j ascending => idx ascending
        }

        // warp argmax reduce, tie-break lowest index
#pragma unroll
        for (int off = 16; off; off >>= 1) {
            float ov = __shfl_down_sync(0xffffffffu, bv, off);
            int   oi = __shfl_down_sync(0xffffffffu, bi, off);
            if (ov > bv || (ov == bv && oi < bi)) { bv = ov; bi = oi; }
        }
        if ((tid & 31) == 0) { swv[tid >> 5] = bv; swi[tid >> 5] = bi; }
        __syncthreads();
        if (tid < 32) {
            bv = swv[tid];
            bi = swi[tid];
#pragma unroll
            for (int off = 16; off; off >>= 1) {
                float ov = __shfl_down_sync(0xffffffffu, bv, off);
                int   oi = __shfl_down_sync(0xffffffffu, bi, off);
                if (ov > bv || (ov == bv && oi < bi)) { bv = ov; bi = oi; }
            }
            if (tid == 0) sBI = bi;
        }
        __syncthreads();
        const int w = sBI;
        if (tid == (w & 1023)) {
            int j = w >> 10;
            sCx = px[j]; sCy = py[j]; sCz = pz[j];
        }
        __syncthreads();
    }
}

// ---------------------------------------------------------------------------
// Kernel 2: fused ball-query + grouping + 3-layer MLP + max-pool.
// One warp per center (lane = neighbor slot). Weights staged in dynamic smem.
// h1/h2 register-resident (fully unrolled), h3 streamed with warp max-reduce.
// ---------------------------------------------------------------------------
__global__ __launch_bounds__(128) void bq_mlp_kernel(
    const float* __restrict__ xyz,
    const float* __restrict__ w1, const float* __restrict__ b1,
    const float* __restrict__ w2, const float* __restrict__ b2,
    const float* __restrict__ w3, const float* __restrict__ b3,
    float* __restrict__ out)
{
    extern __shared__ float sh[];
    float* sW1 = sh;                   // 192
    float* sB1 = sW1 + C1 * 3;         // 64
    float* sW2 = sB1 + C1;             // 4096
    float* sB2 = sW2 + C2 * C1;        // 64
    float* sW3 = sB2 + C2;             // 8192
    float* sB3 = sW3 + C3 * C2;        // 128
    int*   sNbr = (int*)(sB3 + C3);    // 4 warps * 32

    const int tid = threadIdx.x;
    for (int i = tid; i < C1 * 3;  i += 128) sW1[i] = w1[i];
    for (int i = tid; i < C1;      i += 128) sB1[i] = b1[i];
    for (int i = tid; i < C2 * C1; i += 128) sW2[i] = w2[i];
    for (int i = tid; i < C2;      i += 128) sB2[i] = b2[i];
    for (int i = tid; i < C3 * C2; i += 128) sW3[i] = w3[i];
    for (int i = tid; i < C3;      i += 128) sB3[i] = b3[i];
    __syncthreads();

    const int wid  = tid >> 5;
    const int lane = tid & 31;
    const int c    = blockIdx.x * 4 + wid;      // center id, 0..16383
    const int b    = c >> 11;                   // / NS
    const int s    = c & (NS - 1);
    const float* P = xyz + b * NPTS * 3;

    const float cx = g_new_xyz[c * 3 + 0];
    const float cy = g_new_xyz[c * 3 + 1];
    const float cz = g_new_xyz[c * 3 + 2];

    // ---- ball query: first KNB hits in ascending index order ----
    // 0.04f matches JAX weak-typed cast of (0.2*0.2) double -> f32
    const float RR = 0.04f;
    int count = 0;
    int* nb = sNbr + wid * KNB;
    for (int base = 0; base < NPTS && count < KNB; base += 32) {
        int i = base + lane;
        float dx = cx - P[i * 3 + 0];
        float dy = cy - P[i * 3 + 1];
        float dz = cz - P[i * 3 + 2];
        float d2 = sqdist_xla(dx, dy, dz);
        bool hit = (d2 <= RR);
        unsigned m = __ballot_sync(0xffffffffu, hit);
        int pos = count + __popc(m & ((1u << lane) - 1u));
        if (hit && pos < KNB) nb[pos] = i;
        count += __popc(m);
    }
    __syncwarp();
    int cc = count < KNB ? count : KNB;   // >= 1 always (center is a real point)
    if (lane >= cc) nb[lane] = nb[0];     // pad with first hit
    __syncwarp();
    const int ni = nb[lane];

    const float rx = P[ni * 3 + 0] - cx;
    const float ry = P[ni * 3 + 1] - cy;
    const float rz = P[ni * 3 + 2] - cz;

    // ---- layer 1: 3 -> 64 ----
    float h1[C1];
#pragma unroll
    for (int o = 0; o < C1; o++) {
        float a = sB1[o];
        a = fmaf(sW1[o * 3 + 0], rx, a);
        a = fmaf(sW1[o * 3 + 1], ry, a);
        a = fmaf(sW1[o * 3 + 2], rz, a);
        h1[o] = fmaxf(a, 0.0f);
    }

    // ---- layer 2: 64 -> 64 ----
    float h2[C2];
#pragma unroll
    for (int o = 0; o < C2; o++) {
        float a = sB2[o];
#pragma unroll
        for (int i = 0; i < C1; i++) a = fmaf(sW2[o * C1 + i], h1[i], a);
        h2[o] = fmaxf(a, 0.0f);
    }

    // ---- layer 3: 64 -> 128, streamed, warp max over 32 neighbors ----
    float* optr = out + BATCH * 3 * NS + (b * C3) * NS + s;
    for (int o = 0; o < C3; o++) {
        float a = sB3[o];
#pragma unroll
        for (int i = 0; i < C2; i++) a = fmaf(sW3[o * C2 + i], h2[i], a);
        a = fmaxf(a, 0.0f);
#pragma unroll
        for (int off = 16; off; off >>= 1)
            a = fmaxf(a, __shfl_xor_sync(0xffffffffu, a, off));
        if (lane == 0) optr[o * NS] = a;
    }
}

// ---------------------------------------------------------------------------
extern "C" void kernel_launch(void* const* d_in, const int* in_sizes, int n_in,
                              void* d_out, int out_size)
{
    const float* xyz = (const float*)d_in[0];
    // d_in[1] = features, unused by the reference
    const float* w1 = (const float*)d_in[2];
    const float* b1 = (const float*)d_in[3];
    const float* w2 = (const float*)d_in[4];
    const float* b2 = (const float*)d_in[5];
    const float* w3 = (const float*)d_in[6];
    const float* b3 = (const float*)d_in[7];
    float* out = (float*)d_out;

    const int shmem = (C1 * 3 + C1 + C2 * C1 + C2 + C3 * C2 + C3) * 4 + 4 * KNB * 4;
    cudaFuncSetAttribute(bq_mlp_kernel, cudaFuncAttributeMaxDynamicSharedMemorySize, shmem);

    fps_kernel<<<BATCH, 1024>>>(xyz, out);
    bq_mlp_kernel<<<(BATCH * NS) / 4, 128, shmem>>>(xyz, w1, b1, w2, b2, w3, b3, out);
}

// round 3
// speedup vs baseline: 1.6494x; 1.6494x over previous
#include <cuda_runtime.h>

#define BATCH 8
#define NPTS  8192
#define NS    2048      // S = 0.25 * N
#define KNB   32        // nsample
#define C1    64
#define C2    64
#define C3    128

// scratch: new_xyz coords shared between the two kernels
__device__ float g_new_xyz[BATCH * NS * 3];

// XLA-exact squared distance: ((dx*dx + dy*dy) + dz*dz), no FMA contraction
__device__ __forceinline__ float sqdist_xla(float dx, float dy, float dz) {
    return __fadd_rn(__fadd_rn(__fmul_rn(dx, dx), __fmul_rn(dy, dy)),
                     __fmul_rn(dz, dz));
}

__device__ __forceinline__ unsigned long long pack2(float a, float b) {
    unsigned long long r;
    asm("mov.b64 %0, {%1, %2};" : "=l"(r) : "f"(a), "f"(b));
    return r;
}
__device__ __forceinline__ void unpack2(unsigned long long v, float& a, float& b) {
    asm("mov.b64 {%0, %1}, %2;" : "=f"(a), "=f"(b) : "l"(v));
}
__device__ __forceinline__ unsigned long long add2(unsigned long long a, unsigned long long b) {
    unsigned long long r;
    asm("add.rn.f32x2 %0, %1, %2;" : "=l"(r) : "l"(a), "l"(b));
    return r;
}
__device__ __forceinline__ unsigned long long mul2(unsigned long long a, unsigned long long b) {
    unsigned long long r;
    asm("mul.rn.f32x2 %0, %1, %2;" : "=l"(r) : "l"(a), "l"(b));
    return r;
}

// ---------------------------------------------------------------------------
// Kernel 1: farthest point sampling. One CTA (256 threads) per batch.
// 32 points/thread, coords pre-negated + packed for f32x2 distance math
// (per-lane rn results identical to scalar). One __syncthreads per iteration:
// warp leaders post candidates to parity-buffered smem; all threads reduce the
// 8 candidates redundantly and fetch the winning centroid via L1 LDG.
// ---------------------------------------------------------------------------
__global__ __launch_bounds__(256) void fps_kernel(const float* __restrict__ xyz,
                                                  float* __restrict__ out)
{
    const int b   = blockIdx.x;
    const int tid = threadIdx.x;
    const int lane = tid & 31, wid = tid >> 5;
    const float* P = xyz + b * NPTS * 3;

    __shared__ float sV[2][8];
    __shared__ int   sI[2][8];

    unsigned long long npx[16], npy[16], npz[16];
    float dist[32];
#pragma unroll
    for (int m = 0; m < 16; m++) {
        int i0 = tid + (2 * m) * 256;
        int i1 = tid + (2 * m + 1) * 256;
        npx[m] = pack2(-P[i0 * 3 + 0], -P[i1 * 3 + 0]);
        npy[m] = pack2(-P[i0 * 3 + 1], -P[i1 * 3 + 1]);
        npz[m] = pack2(-P[i0 * 3 + 2], -P[i1 * 3 + 2]);
        dist[2 * m] = 1e10f;
        dist[2 * m + 1] = 1e10f;
    }
    float cx = __ldg(P + 0), cy = __ldg(P + 1), cz = __ldg(P + 2);

    for (int s = 0; s < NS; s++) {
        if (tid == 0) {
            int o = b * 3 * NS + s;          // (B,3,S) transposed output
            out[o]          = cx;
            out[o + NS]     = cy;
            out[o + 2 * NS] = cz;
            int c = (b * NS + s) * 3;
            g_new_xyz[c]     = cx;
            g_new_xyz[c + 1] = cy;
            g_new_xyz[c + 2] = cz;
        }

        const unsigned long long cxx = pack2(cx, cx);
        const unsigned long long cyy = pack2(cy, cy);
        const unsigned long long czz = pack2(cz, cz);

        float bv = -1.0f;
        int   bi = 0;
#pragma unroll
        for (int m = 0; m < 16; m++) {
            unsigned long long dx2 = add2(cxx, npx[m]);   // cx - px (exact)
            unsigned long long dy2 = add2(cyy, npy[m]);
            unsigned long long dz2 = add2(czz, npz[m]);
            unsigned long long d2p = add2(add2(mul2(dx2, dx2), mul2(dy2, dy2)),
                                          mul2(dz2, dz2)); // ((x²+y²)+z²) rn
            float d0, d1;
            unpack2(d2p, d0, d1);
            float nd0 = fminf(dist[2 * m], d0);
            dist[2 * m] = nd0;
            if (nd0 > bv) { bv = nd0; bi = tid + (2 * m) * 256; }
            float nd1 = fminf(dist[2 * m + 1], d1);
            dist[2 * m + 1] = nd1;
            if (nd1 > bv) { bv = nd1; bi = tid + (2 * m + 1) * 256; }
        }

        // warp argmax reduce (lexicographic: max value, then lowest index)
#pragma unroll
        for (int off = 16; off; off >>= 1) {
            float ov = __shfl_down_sync(0xffffffffu, bv, off);
            int   oi = __shfl_down_sync(0xffffffffu, bi, off);
            if (ov > bv || (ov == bv && oi < bi)) { bv = ov; bi = oi; }
        }
        const int pb = s & 1;
        if (lane == 0) { sV[pb][wid] = bv; sI[pb][wid] = bi; }
        __syncthreads();

        // every thread reduces the 8 warp candidates redundantly
        float xv = sV[pb][0];
        int   xi = sI[pb][0];
#pragma unroll
        for (int w = 1; w < 8; w++) {
            float cv = sV[pb][w];
            int   ci = sI[pb][w];
            if (cv > xv || (cv == xv && ci < xi)) { xv = cv; xi = ci; }
        }
        cx = __ldg(P + xi * 3 + 0);   // L1-resident broadcast
        cy = __ldg(P + xi * 3 + 1);
        cz = __ldg(P + xi * 3 + 2);
    }
}

// ---------------------------------------------------------------------------
// Kernel 2: fused ball-query + grouping + 3-layer MLP + max-pool.
// One warp per center (lane = neighbor). Layer 1+2 computed incrementally
// (h1_i produced then immediately scattered into h2 accumulators through
// transposed W2) so h1 never occupies registers. 4 CTAs/SM.
// ---------------------------------------------------------------------------
__global__ __launch_bounds__(128, 4) void bq_mlp_kernel(
    const float* __restrict__ xyz,
    const float* __restrict__ w1, const float* __restrict__ b1,
    const float* __restrict__ w2, const float* __restrict__ b2,
    const float* __restrict__ w3, const float* __restrict__ b3,
    float* __restrict__ out)
{
    extern __shared__ float sh[];
    float* sW1  = sh;                    // 192
    float* sB1  = sW1 + C1 * 3;          // 64
    float* sW2t = sB1 + C1;              // 4096 (transposed: [i][o])
    float* sB2  = sW2t + C2 * C1;        // 64
    float* sW3  = sB2 + C2;              // 8192
    float* sB3  = sW3 + C3 * C2;         // 128
    int*   sNbr = (int*)(sB3 + C3);      // 4 warps * 32

    const int tid = threadIdx.x;
    for (int i = tid; i < C1 * 3;  i += 128) sW1[i] = w1[i];
    for (int i = tid; i < C1;      i += 128) sB1[i] = b1[i];
    for (int i = tid; i < C2 * C1; i += 128) {
        int o = i >> 6, ii = i & 63;
        sW2t[ii * C2 + o] = w2[i];
    }
    for (int i = tid; i < C2;      i += 128) sB2[i] = b2[i];
    for (int i = tid; i < C3 * C2; i += 128) sW3[i] = w3[i];
    for (int i = tid; i < C3;      i += 128) sB3[i] = b3[i];
    __syncthreads();

    const int wid  = tid >> 5;
    const int lane = tid & 31;
    const int c    = blockIdx.x * 4 + wid;      // center id, 0..16383
    const int b    = c >> 11;                   // / NS
    const int s    = c & (NS - 1);
    const float* P = xyz + b * NPTS * 3;

    const float cx = g_new_xyz[c * 3 + 0];
    const float cy = g_new_xyz[c * 3 + 1];
    const float cz = g_new_xyz[c * 3 + 2];

    // ---- ball query: first KNB hits in ascending index order ----
    const float RR = 0.04f;   // JAX weak-typed (0.2*0.2) double -> f32
    int count = 0;
    int* nb = sNbr + wid * KNB;
    for (int base = 0; base < NPTS && count < KNB; base += 32) {
        int i = base + lane;
        float dx = cx - P[i * 3 + 0];
        float dy = cy - P[i * 3 + 1];
        float dz = cz - P[i * 3 + 2];
        float d2 = sqdist_xla(dx, dy, dz);
        bool hit = (d2 <= RR);
        unsigned m = __ballot_sync(0xffffffffu, hit);
        int pos = count + __popc(m & ((1u << lane) - 1u));
        if (hit && pos < KNB) nb[pos] = i;
        count += __popc(m);
    }
    __syncwarp();
    int cc = count < KNB ? count : KNB;   // >= 1 always
    if (lane >= cc) nb[lane] = nb[0];     // pad with first hit
    __syncwarp();
    const int ni = nb[lane];

    const float rx = P[ni * 3 + 0] - cx;
    const float ry = P[ni * 3 + 1] - cy;
    const float rz = P[ni * 3 + 2] - cz;

    // ---- layers 1+2 fused: h2[o] = b2[o] + sum_i W2[o][i]*relu(W1[i]·rel+b1[i])
    float acc[C2];
#pragma unroll
    for (int o = 0; o < C2; o++) acc[o] = sB2[o];

#pragma unroll 4
    for (int i = 0; i < C1; i++) {
        float a = sB1[i];
        a = fmaf(sW1[i * 3 + 0], rx, a);
        a = fmaf(sW1[i * 3 + 1], ry, a);
        a = fmaf(sW1[i * 3 + 2], rz, a);
        float h1 = fmaxf(a, 0.0f);
        const float4* w4 = reinterpret_cast<const float4*>(sW2t + (i << 6));
#pragma unroll
        for (int o4 = 0; o4 < 16; o4++) {
            float4 w = w4[o4];
            acc[o4 * 4 + 0] = fmaf(w.x, h1, acc[o4 * 4 + 0]);
            acc[o4 * 4 + 1] = fmaf(w.y, h1, acc[o4 * 4 + 1]);
            acc[o4 * 4 + 2] = fmaf(w.z, h1, acc[o4 * 4 + 2]);
            acc[o4 * 4 + 3] = fmaf(w.w, h1, acc[o4 * 4 + 3]);
        }
    }
#pragma unroll
    for (int o = 0; o < C2; o++) acc[o] = fmaxf(acc[o], 0.0f);

    // ---- layer 3: 64 -> 128, streamed, warp max over 32 neighbors ----
    float* optr = out + BATCH * 3 * NS + (b * C3) * NS + s;
#pragma unroll 2
    for (int o = 0; o < C3; o++) {
        const float4* w4 = reinterpret_cast<const float4*>(sW3 + (o << 6));
        float a = sB3[o];
#pragma unroll
        for (int i4 = 0; i4 < 16; i4++) {
            float4 w = w4[i4];
            a = fmaf(w.x, acc[i4 * 4 + 0], a);
            a = fmaf(w.y, acc[i4 * 4 + 1], a);
            a = fmaf(w.z, acc[i4 * 4 + 2], a);
            a = fmaf(w.w, acc[i4 * 4 + 3], a);
        }
        a = fmaxf(a, 0.0f);
#pragma unroll
        for (int off = 16; off; off >>= 1)
            a = fmaxf(a, __shfl_xor_sync(0xffffffffu, a, off));
        if (lane == 0) optr[o * NS] = a;
    }
}

// ---------------------------------------------------------------------------
extern "C" void kernel_launch(void* const* d_in, const int* in_sizes, int n_in,
                              void* d_out, int out_size)
{
    const float* xyz = (const float*)d_in[0];
    // d_in[1] = features, unused by the reference
    const float* w1 = (const float*)d_in[2];
    const float* b1 = (const float*)d_in[3];
    const float* w2 = (const float*)d_in[4];
    const float* b2 = (const float*)d_in[5];
    const float* w3 = (const float*)d_in[6];
    const float* b3 = (const float*)d_in[7];
    float* out = (float*)d_out;

    const int shmem = (C1 * 3 + C1 + C2 * C1 + C2 + C3 * C2 + C3) * 4 + 4 * KNB * 4;
    cudaFuncSetAttribute(bq_mlp_kernel, cudaFuncAttributeMaxDynamicSharedMemorySize, shmem);

    fps_kernel<<<BATCH, 256>>>(xyz, out);
    bq_mlp_kernel<<<(BATCH * NS) / 4, 128, shmem>>>(xyz, w1, b1, w2, b2, w3, b3, out);
}